// round 6
// baseline (speedup 1.0000x reference)
#include <cuda_runtime.h>

// PZCell biquad, warp-per-row parallel scan, 4-quarter cp.async pipeline.
// y[t] = b0 x[t] + b1 x[t-1] + b2 x[t-2] - a1 y[t-1] - a2 y[t-2]   (den == 1)
// Per warp (one row): 4 quarters of 512 steps; each quarter = 32 lanes x 16
// steps in a swizzled 2KB SMEM tile. All 4 quarter loads issued up front as
// separate cp.async groups; per quarter: Phase A zero-state recurrence in
// place -> seeded affine Kogge-Stone scan (carry folded into lane0 seed) ->
// store pass with fused homogeneous correction (W = M^f0 per lane).

namespace {
constexpr int T_LEN   = 2048;
constexpr int B_ROWS  = 4096;
constexpr int QSTEPS  = 512;                // steps per quarter
constexpr int NQ      = 4;
constexpr int QTILE   = 512;                // floats per quarter buffer (2KB)
constexpr int RPB     = 2;                  // rows (warps) per block
constexpr int THREADS = 32 * RPB;
constexpr int WARP_SMEM  = NQ * QTILE;      // 2048 floats
constexpr int SMEM_BYTES = RPB * WARP_SMEM * (int)sizeof(float);  // 16384
}

// chunk c (0..31, 16 floats), granule g (0..3): conflict-free for all passes
__device__ __forceinline__ int swz(int c, int g) {
    return c * 16 + ((g ^ ((c >> 1) & 3)) << 2);
}

__device__ __forceinline__ void cp_async16(float* dst, const float* src) {
    unsigned s = (unsigned)__cvta_generic_to_shared(dst);
    asm volatile("cp.async.cg.shared.global [%0], [%1], 16;" :: "r"(s), "l"(src));
}
__device__ __forceinline__ void cp_commit() { asm volatile("cp.async.commit_group;"); }
template <int N>
__device__ __forceinline__ void cp_wait() {
    asm volatile("cp.async.wait_group %0;" :: "n"(N) : "memory");
}

struct Coef { float a1, a2, A2, Bc, b0, b1, b2; };
struct Mat  { float m00, m01, m10, m11; };

__device__ __forceinline__ Mat mat_sq(const Mat& a) {
    Mat r;
    r.m00 = a.m00*a.m00 + a.m01*a.m10;  r.m01 = a.m00*a.m01 + a.m01*a.m11;
    r.m10 = a.m10*a.m00 + a.m11*a.m10;  r.m11 = a.m10*a.m01 + a.m11*a.m11;
    return r;
}
__device__ __forceinline__ Mat mat_mul(const Mat& a, const Mat& b) {
    Mat r;
    r.m00 = a.m00*b.m00 + a.m01*b.m10;  r.m01 = a.m00*b.m01 + a.m01*b.m11;
    r.m10 = a.m10*b.m00 + a.m11*b.m10;  r.m11 = a.m10*b.m01 + a.m11*b.m11;
    return r;
}

// one 512-step quarter. Px,Py = row exit state (updated); bx1,bx2 = x tail
// of previous quarter (updated to this quarter's tail).
__device__ __forceinline__ void quarter_pass(
    float* buf, float* __restrict__ yq, int lane, const Coef& c,
    const Mat& W, const Mat& M16, float& Px, float& Py, float& bx1, float& bx2)
{
    // ---- boundary x[-1], x[-2] ----
    float x1, x2;
    if (lane > 0) {
        int cc = lane - 1;
        int off = cc * 16 + ((3 ^ ((cc >> 1) & 3)) << 2);   // granule 3 = f 12..15
        x1 = buf[off + 3];   // f=15
        x2 = buf[off + 2];   // f=14
    } else {
        x1 = bx1; x2 = bx2;
    }
    __syncwarp();

    // ---- Phase A: zero-entry-state recurrence in place ----
    float p = 0.f, q = 0.f;
    #pragma unroll
    for (int g = 0; g < 4; ++g) {
        float4 xv = *reinterpret_cast<float4*>(buf + swz(lane, g));
        float u0 = fmaf(c.b0, xv.x, fmaf(c.b1, x1,   c.b2 * x2));
        float u1 = fmaf(c.b0, xv.y, fmaf(c.b1, xv.x, c.b2 * x1));
        float u2 = fmaf(c.b0, xv.z, fmaf(c.b1, xv.y, c.b2 * xv.x));
        float u3 = fmaf(c.b0, xv.w, fmaf(c.b1, xv.z, c.b2 * xv.y));
        x2 = xv.z; x1 = xv.w;
        float w1 = fmaf(-c.a1, u0, u1);
        float w3 = fmaf(-c.a1, u2, u3);
        float yA = fmaf(-c.a1, p,  fmaf(-c.a2, q,  u0));
        float yB = fmaf( c.A2, p,  fmaf( c.Bc, q,  w1));
        float yC = fmaf(-c.a1, yB, fmaf(-c.a2, yA, u2));
        float yD = fmaf( c.A2, yB, fmaf( c.Bc, yA, w3));
        p = yD; q = yC;
        *reinterpret_cast<float4*>(buf + swz(lane, g)) = make_float4(yA, yB, yC, yD);
    }
    // x tail of this quarter (lane 31 holds x[511], x[510])
    float nbx1 = __shfl_sync(0xffffffffu, x1, 31);
    float nbx2 = __shfl_sync(0xffffffffu, x2, 31);
    bx1 = nbx1; bx2 = nbx2;

    // ---- seeded affine Kogge-Stone scan (T = M^16) ----
    Mat m = M16;
    float vx = p, vy = q;
    if (lane == 0) {   // fold row carry into seed: d0' = d0 + T*P
        vx = fmaf(m.m00, Px, fmaf(m.m01, Py, vx));
        vy = fmaf(m.m10, Px, fmaf(m.m11, Py, vy));
    }
    #pragma unroll
    for (int i = 0; i < 5; ++i) {
        float ox = __shfl_up_sync(0xffffffffu, vx, 1u << i);
        float oy = __shfl_up_sync(0xffffffffu, vy, 1u << i);
        if (lane >= (1 << i)) {
            vx = fmaf(m.m00, ox, fmaf(m.m01, oy, vx));
            vy = fmaf(m.m10, ox, fmaf(m.m11, oy, vy));
        }
        if (i < 4) m = mat_sq(m);
    }
    // entry state per chunk (exclusive); lane 0 entry = carried P
    float ex = __shfl_up_sync(0xffffffffu, vx, 1);
    float ey = __shfl_up_sync(0xffffffffu, vy, 1);
    if (lane == 0) { ex = Px; ey = Py; }
    // row exit state = inclusive at lane 31 (carry included via seed)
    Px = __shfl_sync(0xffffffffu, vx, 31);
    Py = __shfl_sync(0xffffffffu, vy, 31);

    __syncwarp();

    // ---- store pass with fused homogeneous correction ----
    // lane covers granule (lane&3) of chunk k*8+(lane>>2): f0 = (lane&3)*4.
    // seed (h[f0-1], h[f0-2]) = W * entry,  W = M^f0.
    #pragma unroll
    for (int k = 0; k < 4; ++k) {
        int ch = k * 8 + (lane >> 2);
        float exc = __shfl_sync(0xffffffffu, ex, ch);
        float eyc = __shfl_sync(0xffffffffu, ey, ch);
        float s1 = fmaf(W.m00, exc, W.m01 * eyc);
        float s2 = fmaf(W.m10, exc, W.m11 * eyc);
        float hA = fmaf(-c.a1, s1, -c.a2 * s2);
        float hB = fmaf( c.A2, s1,  c.Bc * s2);
        float hC = fmaf(-c.a1, hB, -c.a2 * hA);
        float hD = fmaf( c.A2, hB,  c.Bc * hA);
        float4 zv = *reinterpret_cast<float4*>(buf + swz(ch, lane & 3));
        zv.x += hA; zv.y += hB; zv.z += hC; zv.w += hD;
        *reinterpret_cast<float4*>(yq + k * 128 + lane * 4) = zv;
    }
    __syncwarp();
}

__global__ void __launch_bounds__(THREADS, 14)
pz6_kernel(const float* __restrict__ x, const float* __restrict__ gain_ri,
           const float* __restrict__ poles_ri, const float* __restrict__ zeros_ri,
           float* __restrict__ out)
{
    extern __shared__ float sbuf[];
    const int lane = threadIdx.x & 31;
    const int w    = threadIdx.x >> 5;
    const int row  = blockIdx.x * RPB + w;
    const float* xr = x   + (long)row * T_LEN;
    float*       yr = out + (long)row * T_LEN;
    float* sb = sbuf + w * WARP_SMEM;

    // ---- issue all 4 quarter loads (4 commit groups) ----
    #pragma unroll
    for (int qi = 0; qi < NQ; ++qi) {
        float* buf = sb + qi * QTILE;
        const float* xq = xr + qi * QSTEPS;
        #pragma unroll
        for (int k = 0; k < 4; ++k) {
            int ch = k * 8 + (lane >> 2);
            cp_async16(buf + swz(ch, lane & 3), xq + k * 128 + lane * 4);
        }
        cp_commit();
    }

    // ---- coefficients + matrix powers (overlaps with cp.async) ----
    Coef c;
    {
        const float gr = gain_ri[0],  gi = gain_ri[1];
        const float pr0 = poles_ri[0], pi0 = poles_ri[1];
        const float pr1 = poles_ri[2], pi1 = poles_ri[3];
        const float zr0 = zeros_ri[0], zi0 = zeros_ri[1];
        const float zr1 = zeros_ri[2], zi1 = zeros_ri[3];
        c.a1 = -(pr0 + pr1);
        c.a2 = pr0 * pr1 - pi0 * pi1;
        const float zc1r = -(zr0 + zr1), zc1i = -(zi0 + zi1);
        const float zc2r = zr0 * zr1 - zi0 * zi1;
        const float zc2i = zr0 * zi1 + zi0 * zr1;
        c.b0 = gr;
        c.b1 = gr * zc1r - gi * zc1i;
        c.b2 = gr * zc2r - gi * zc2i;
        c.A2 = c.a1 * c.a1 - c.a2;
        c.Bc = c.a1 * c.a2;
    }
    Mat M1 = { -c.a1, -c.a2, 1.f, 0.f };
    Mat M2  = mat_sq(M1);
    Mat M4  = mat_sq(M2);
    Mat M8  = mat_sq(M4);
    Mat M16 = mat_sq(M8);
    Mat W = { 1.f, 0.f, 0.f, 1.f };           // W = M^(4*(lane&3))
    if (lane & 1) W = M4;
    if (lane & 2) W = mat_mul(M8, W);

    float Px = 0.f, Py = 0.f;     // row exit state carry
    float bx1 = 0.f, bx2 = 0.f;   // x tail carry

    cp_wait<3>(); __syncwarp();
    quarter_pass(sb + 0 * QTILE, yr + 0 * QSTEPS, lane, c, W, M16, Px, Py, bx1, bx2);
    cp_wait<2>(); __syncwarp();
    quarter_pass(sb + 1 * QTILE, yr + 1 * QSTEPS, lane, c, W, M16, Px, Py, bx1, bx2);
    cp_wait<1>(); __syncwarp();
    quarter_pass(sb + 2 * QTILE, yr + 2 * QSTEPS, lane, c, W, M16, Px, Py, bx1, bx2);
    cp_wait<0>(); __syncwarp();
    quarter_pass(sb + 3 * QTILE, yr + 3 * QSTEPS, lane, c, W, M16, Px, Py, bx1, bx2);
}

extern "C" void kernel_launch(void* const* d_in, const int* in_sizes, int n_in,
                              void* d_out, int out_size) {
    (void)in_sizes; (void)n_in; (void)out_size;
    const float* x        = (const float*)d_in[0];
    const float* gain_ri  = (const float*)d_in[1];
    const float* poles_ri = (const float*)d_in[2];
    const float* zeros_ri = (const float*)d_in[3];
    float* out = (float*)d_out;

    cudaFuncSetAttribute(pz6_kernel, cudaFuncAttributeMaxDynamicSharedMemorySize, SMEM_BYTES);
    pz6_kernel<<<B_ROWS / RPB, THREADS, SMEM_BYTES>>>(x, gain_ri, poles_ri, zeros_ri, out);
}

// round 7
// speedup vs baseline: 1.1003x; 1.1003x over previous
#include <cuda_runtime.h>

// PZCell biquad, warp-per-row parallel scan, 3-buffer cp.async ring.
// y[t] = b0 x[t] + b1 x[t-1] + b2 x[t-2] - a1 y[t-1] - a2 y[t-2]   (den == 1)
// Per warp (one row): 4 quarters of 512 steps; each quarter = 32 lanes x 16
// steps in a swizzled 2KB SMEM tile. 3-buffer ring: q3 reuses buf0 after q0
// drains. Per quarter: Phase A zero-state recurrence in place -> seeded
// affine Kogge-Stone scan -> store pass with fused homogeneous correction.

namespace {
constexpr int T_LEN   = 2048;
constexpr int B_ROWS  = 4096;
constexpr int QSTEPS  = 512;                // steps per quarter
constexpr int QTILE   = 512;                // floats per quarter buffer (2KB)
constexpr int NBUF    = 3;                  // ring buffers
constexpr int RPB     = 2;                  // rows (warps) per block
constexpr int THREADS = 32 * RPB;
constexpr int WARP_SMEM  = NBUF * QTILE;    // 1536 floats
constexpr int SMEM_BYTES = RPB * WARP_SMEM * (int)sizeof(float);  // 12288
}

// chunk c (0..31, 16 floats), granule g (0..3): conflict-free for all passes
__device__ __forceinline__ int swz(int c, int g) {
    return c * 16 + ((g ^ ((c >> 1) & 3)) << 2);
}

__device__ __forceinline__ void cp_async16(float* dst, const float* src) {
    unsigned s = (unsigned)__cvta_generic_to_shared(dst);
    asm volatile("cp.async.cg.shared.global [%0], [%1], 16;" :: "r"(s), "l"(src));
}
__device__ __forceinline__ void cp_commit() { asm volatile("cp.async.commit_group;"); }
template <int N>
__device__ __forceinline__ void cp_wait() {
    asm volatile("cp.async.wait_group %0;" :: "n"(N) : "memory");
}

struct Coef { float a1, a2, A2, Bc, b0, b1, b2; };
struct Mat  { float m00, m01, m10, m11; };

__device__ __forceinline__ Mat mat_sq(const Mat& a) {
    Mat r;
    r.m00 = a.m00*a.m00 + a.m01*a.m10;  r.m01 = a.m00*a.m01 + a.m01*a.m11;
    r.m10 = a.m10*a.m00 + a.m11*a.m10;  r.m11 = a.m10*a.m01 + a.m11*a.m11;
    return r;
}
__device__ __forceinline__ Mat mat_mul(const Mat& a, const Mat& b) {
    Mat r;
    r.m00 = a.m00*b.m00 + a.m01*b.m10;  r.m01 = a.m00*b.m01 + a.m01*b.m11;
    r.m10 = a.m10*b.m00 + a.m11*b.m10;  r.m11 = a.m10*b.m01 + a.m11*b.m11;
    return r;
}

// issue one quarter's coalesced cp.async load into buf
__device__ __forceinline__ void issue_quarter_load(
    float* buf, const float* __restrict__ xq, int lane)
{
    #pragma unroll
    for (int k = 0; k < 4; ++k) {
        int ch = k * 8 + (lane >> 2);
        cp_async16(buf + swz(ch, lane & 3), xq + k * 128 + lane * 4);
    }
    cp_commit();
}

// one 512-step quarter. Px,Py = row exit state (updated); bx1,bx2 = x tail
// of previous quarter (updated to this quarter's tail).
__device__ __forceinline__ void quarter_pass(
    float* buf, float* __restrict__ yq, int lane, const Coef& c,
    const Mat& W, const Mat& M16, float& Px, float& Py, float& bx1, float& bx2)
{
    // ---- boundary x[-1], x[-2] ----
    float x1, x2;
    if (lane > 0) {
        int cc = lane - 1;
        int off = cc * 16 + ((3 ^ ((cc >> 1) & 3)) << 2);   // granule 3 = f 12..15
        x1 = buf[off + 3];   // f=15
        x2 = buf[off + 2];   // f=14
    } else {
        x1 = bx1; x2 = bx2;
    }
    __syncwarp();

    // ---- Phase A: zero-entry-state recurrence in place ----
    float p = 0.f, q = 0.f;
    #pragma unroll
    for (int g = 0; g < 4; ++g) {
        float4 xv = *reinterpret_cast<float4*>(buf + swz(lane, g));
        float u0 = fmaf(c.b0, xv.x, fmaf(c.b1, x1,   c.b2 * x2));
        float u1 = fmaf(c.b0, xv.y, fmaf(c.b1, xv.x, c.b2 * x1));
        float u2 = fmaf(c.b0, xv.z, fmaf(c.b1, xv.y, c.b2 * xv.x));
        float u3 = fmaf(c.b0, xv.w, fmaf(c.b1, xv.z, c.b2 * xv.y));
        x2 = xv.z; x1 = xv.w;
        float w1 = fmaf(-c.a1, u0, u1);
        float w3 = fmaf(-c.a1, u2, u3);
        float yA = fmaf(-c.a1, p,  fmaf(-c.a2, q,  u0));
        float yB = fmaf( c.A2, p,  fmaf( c.Bc, q,  w1));
        float yC = fmaf(-c.a1, yB, fmaf(-c.a2, yA, u2));
        float yD = fmaf( c.A2, yB, fmaf( c.Bc, yA, w3));
        p = yD; q = yC;
        *reinterpret_cast<float4*>(buf + swz(lane, g)) = make_float4(yA, yB, yC, yD);
    }
    // x tail of this quarter (lane 31 holds x[511], x[510])
    float nbx1 = __shfl_sync(0xffffffffu, x1, 31);
    float nbx2 = __shfl_sync(0xffffffffu, x2, 31);
    bx1 = nbx1; bx2 = nbx2;

    // ---- seeded affine Kogge-Stone scan (T = M^16) ----
    Mat m = M16;
    float vx = p, vy = q;
    if (lane == 0) {   // fold row carry into seed: d0' = d0 + T*P
        vx = fmaf(m.m00, Px, fmaf(m.m01, Py, vx));
        vy = fmaf(m.m10, Px, fmaf(m.m11, Py, vy));
    }
    #pragma unroll
    for (int i = 0; i < 5; ++i) {
        float ox = __shfl_up_sync(0xffffffffu, vx, 1u << i);
        float oy = __shfl_up_sync(0xffffffffu, vy, 1u << i);
        if (lane >= (1 << i)) {
            vx = fmaf(m.m00, ox, fmaf(m.m01, oy, vx));
            vy = fmaf(m.m10, ox, fmaf(m.m11, oy, vy));
        }
        if (i < 4) m = mat_sq(m);
    }
    // entry state per chunk (exclusive); lane 0 entry = carried P
    float ex = __shfl_up_sync(0xffffffffu, vx, 1);
    float ey = __shfl_up_sync(0xffffffffu, vy, 1);
    if (lane == 0) { ex = Px; ey = Py; }
    // row exit state = inclusive at lane 31 (carry included via seed)
    Px = __shfl_sync(0xffffffffu, vx, 31);
    Py = __shfl_sync(0xffffffffu, vy, 31);

    __syncwarp();

    // ---- store pass with fused homogeneous correction ----
    // lane covers granule (lane&3) of chunk k*8+(lane>>2): f0 = (lane&3)*4.
    // seed (h[f0-1], h[f0-2]) = W * entry,  W = M^f0.
    #pragma unroll
    for (int k = 0; k < 4; ++k) {
        int ch = k * 8 + (lane >> 2);
        float exc = __shfl_sync(0xffffffffu, ex, ch);
        float eyc = __shfl_sync(0xffffffffu, ey, ch);
        float s1 = fmaf(W.m00, exc, W.m01 * eyc);
        float s2 = fmaf(W.m10, exc, W.m11 * eyc);
        float hA = fmaf(-c.a1, s1, -c.a2 * s2);
        float hB = fmaf( c.A2, s1,  c.Bc * s2);
        float hC = fmaf(-c.a1, hB, -c.a2 * hA);
        float hD = fmaf( c.A2, hB,  c.Bc * hA);
        float4 zv = *reinterpret_cast<float4*>(buf + swz(ch, lane & 3));
        zv.x += hA; zv.y += hB; zv.z += hC; zv.w += hD;
        *reinterpret_cast<float4*>(yq + k * 128 + lane * 4) = zv;
    }
    __syncwarp();
}

__global__ void __launch_bounds__(THREADS, 16)
pz7_kernel(const float* __restrict__ x, const float* __restrict__ gain_ri,
           const float* __restrict__ poles_ri, const float* __restrict__ zeros_ri,
           float* __restrict__ out)
{
    extern __shared__ float sbuf[];
    const int lane = threadIdx.x & 31;
    const int w    = threadIdx.x >> 5;
    const int row  = blockIdx.x * RPB + w;
    const float* xr = x   + (long)row * T_LEN;
    float*       yr = out + (long)row * T_LEN;
    float* sb = sbuf + w * WARP_SMEM;

    // ---- issue loads for quarters 0..2 (3 commit groups) ----
    issue_quarter_load(sb + 0 * QTILE, xr + 0 * QSTEPS, lane);
    issue_quarter_load(sb + 1 * QTILE, xr + 1 * QSTEPS, lane);
    issue_quarter_load(sb + 2 * QTILE, xr + 2 * QSTEPS, lane);

    // ---- coefficients + matrix powers (overlaps with cp.async) ----
    Coef c;
    {
        const float gr = gain_ri[0],  gi = gain_ri[1];
        const float pr0 = poles_ri[0], pi0 = poles_ri[1];
        const float pr1 = poles_ri[2], pi1 = poles_ri[3];
        const float zr0 = zeros_ri[0], zi0 = zeros_ri[1];
        const float zr1 = zeros_ri[2], zi1 = zeros_ri[3];
        c.a1 = -(pr0 + pr1);
        c.a2 = pr0 * pr1 - pi0 * pi1;
        const float zc1r = -(zr0 + zr1), zc1i = -(zi0 + zi1);
        const float zc2r = zr0 * zr1 - zi0 * zi1;
        const float zc2i = zr0 * zi1 + zi0 * zr1;
        c.b0 = gr;
        c.b1 = gr * zc1r - gi * zc1i;
        c.b2 = gr * zc2r - gi * zc2i;
        c.A2 = c.a1 * c.a1 - c.a2;
        c.Bc = c.a1 * c.a2;
    }
    Mat M1 = { -c.a1, -c.a2, 1.f, 0.f };
    Mat M4  = mat_sq(mat_sq(M1));
    Mat M8  = mat_sq(M4);
    Mat M16 = mat_sq(M8);
    Mat W = { 1.f, 0.f, 0.f, 1.f };           // W = M^(4*(lane&3))
    if (lane & 1) W = M4;
    if (lane & 2) W = mat_mul(M8, W);

    float Px = 0.f, Py = 0.f;     // row exit state carry
    float bx1 = 0.f, bx2 = 0.f;   // x tail carry

    cp_wait<2>(); __syncwarp();   // q0 resident
    quarter_pass(sb + 0 * QTILE, yr + 0 * QSTEPS, lane, c, W, M16, Px, Py, bx1, bx2);

    // buf0 drained -> issue q3 into it (hidden under q1+q2 compute)
    issue_quarter_load(sb + 0 * QTILE, xr + 3 * QSTEPS, lane);

    cp_wait<2>(); __syncwarp();   // q1 resident (q2, q3 may be outstanding)
    quarter_pass(sb + 1 * QTILE, yr + 1 * QSTEPS, lane, c, W, M16, Px, Py, bx1, bx2);
    cp_wait<1>(); __syncwarp();   // q2 resident
    quarter_pass(sb + 2 * QTILE, yr + 2 * QSTEPS, lane, c, W, M16, Px, Py, bx1, bx2);
    cp_wait<0>(); __syncwarp();   // q3 resident
    quarter_pass(sb + 0 * QTILE, yr + 3 * QSTEPS, lane, c, W, M16, Px, Py, bx1, bx2);
}

extern "C" void kernel_launch(void* const* d_in, const int* in_sizes, int n_in,
                              void* d_out, int out_size) {
    (void)in_sizes; (void)n_in; (void)out_size;
    const float* x        = (const float*)d_in[0];
    const float* gain_ri  = (const float*)d_in[1];
    const float* poles_ri = (const float*)d_in[2];
    const float* zeros_ri = (const float*)d_in[3];
    float* out = (float*)d_out;

    cudaFuncSetAttribute(pz7_kernel, cudaFuncAttributeMaxDynamicSharedMemorySize, SMEM_BYTES);
    pz7_kernel<<<B_ROWS / RPB, THREADS, SMEM_BYTES>>>(x, gain_ri, poles_ri, zeros_ri, out);
}